// round 1
// baseline (speedup 1.0000x reference)
#include <cuda_runtime.h>

namespace {

constexpr int NTOK  = 64;   // tokens per window (8x8)
constexpr int HD    = 32;   // head dim
constexpr int NHEAD = 16;
constexpr int SS    = 4;    // shift size
// pads chosen: row length 68 floats -> 16B-aligned float4 rows, banks (4*row + col) % 32

__global__ __launch_bounds__(128)
void swin_attn_kernel(const float* __restrict__ gq,
                      const float* __restrict__ gk,
                      const float* __restrict__ gv,
                      const float* __restrict__ gbias,
                      float* __restrict__ gout)
{
    __shared__ float Qs[HD][NTOK + 4];    // transposed: Qs[k][i] = Q[i][k]*scale
    __shared__ float Ks[HD][NTOK + 4];    // transposed: Ks[k][j] = K[j][k]
    __shared__ float Vs[NTOK][HD];        // row-major
    __shared__ float St[NTOK][NTOK + 4];  // transposed logits/probs: St[j][i]
    __shared__ float biasS[225];
    __shared__ float rowinv[NTOK];
    __shared__ int   regS[NTOK];

    const int tid   = threadIdx.x;
    const int head  = blockIdx.x & 15;
    const int wy    = blockIdx.x >> 4;
    const int b     = wy >> 6;
    const int win   = wy & 63;
    const int win_h = win >> 3;
    const int win_w = win & 7;
    const float scale = 0.17677669529663687f;  // 1/sqrt(32)

    // ---- load Q,K,V for this (window, head); gather applies the cyclic shift ----
    for (int f = tid; f < 512; f += 128) {          // 512 float4 units per matrix
        int n  = f >> 3;                            // token in window
        int c  = (f & 7) << 2;                      // channel within head (mult of 4)
        int sh = ((win_h << 3) + (n >> 3) + SS) & 63;  // source row (roll by -ss)
        int sw = ((win_w << 3) + (n & 7) + SS) & 63;   // source col
        int base = ((b * 64 + sh) * 64 + sw) * 512 + head * HD + c;
        const float4 qv = *reinterpret_cast<const float4*>(gq + base);
        const float4 kv = *reinterpret_cast<const float4*>(gk + base);
        const float4 vv = *reinterpret_cast<const float4*>(gv + base);
        Qs[c + 0][n] = qv.x * scale; Qs[c + 1][n] = qv.y * scale;
        Qs[c + 2][n] = qv.z * scale; Qs[c + 3][n] = qv.w * scale;
        Ks[c + 0][n] = kv.x; Ks[c + 1][n] = kv.y;
        Ks[c + 2][n] = kv.z; Ks[c + 3][n] = kv.w;
        *reinterpret_cast<float4*>(&Vs[n][c]) = vv;
    }
    // relative position bias slice for this head
    for (int t = tid; t < 225; t += 128) biasS[t] = gbias[t * NHEAD + head];
    // shifted-window region id per token (on the SHIFTED grid)
    if (tid < 64) {
        int hs = (win_h << 3) + (tid >> 3);
        int ws = (win_w << 3) + (tid & 7);
        int rh = (hs >= 56) + (hs >= 60);   // H-ws=56, H-ss=60
        int rw = (ws >= 56) + (ws >= 60);
        regS[tid] = rh * 4 + rw;
    }
    __syncthreads();

    // ---- GEMM1: S = Q*scale @ K^T  (+bias +mask), stored transposed St[j][i] ----
    #pragma unroll
    for (int t2 = 0; t2 < 2; ++t2) {
        int tile = tid + (t2 << 7);         // 256 tiles of 4x4 over 64x64
        int i0 = (tile >> 4) << 2;
        int j0 = (tile & 15) << 2;
        float acc[4][4] = {};
        #pragma unroll
        for (int kk = 0; kk < HD; ++kk) {
            float4 q4 = *reinterpret_cast<const float4*>(&Qs[kk][i0]);
            float4 k4 = *reinterpret_cast<const float4*>(&Ks[kk][j0]);
            float qa[4] = {q4.x, q4.y, q4.z, q4.w};
            float ka[4] = {k4.x, k4.y, k4.z, k4.w};
            #pragma unroll
            for (int a = 0; a < 4; ++a)
                #pragma unroll
                for (int c2 = 0; c2 < 4; ++c2)
                    acc[a][c2] += qa[a] * ka[c2];
        }
        #pragma unroll
        for (int bb = 0; bb < 4; ++bb) {
            int j = j0 + bb;
            int rj = j >> 3, cj = j & 7;
            int regj = regS[j];
            float4 sv;
            float* s = &sv.x;
            #pragma unroll
            for (int a = 0; a < 4; ++a) {
                int i = i0 + a;
                int idx = ((i >> 3) - rj + 7) * 15 + ((i & 7) - cj + 7);
                float val = acc[a][bb] + biasS[idx];
                if (regS[i] != regj) val -= 100.0f;
                s[a] = val;
            }
            *reinterpret_cast<float4*>(&St[j][i0]) = sv;
        }
    }
    __syncthreads();

    // ---- softmax over j (rows of S == columns of St) ----
    if (tid < 64) {
        float mx = -1e30f;
        #pragma unroll 8
        for (int j = 0; j < 64; ++j) mx = fmaxf(mx, St[j][tid]);
        float sum = 0.0f;
        #pragma unroll 8
        for (int j = 0; j < 64; ++j) {
            float p = __expf(St[j][tid] - mx);
            St[j][tid] = p;
            sum += p;
        }
        rowinv[tid] = 1.0f / sum;
    }
    __syncthreads();

    // ---- GEMM2: O = P @ V, normalize, scatter to output with reverse shift ----
    {
        int i0 = (tid >> 3) << 2;   // 16 i-tiles
        int k0 = (tid & 7) << 2;    // 8  k-tiles
        float acc[4][4] = {};
        #pragma unroll
        for (int j = 0; j < NTOK; ++j) {
            float4 p4 = *reinterpret_cast<const float4*>(&St[j][i0]);
            float4 v4 = *reinterpret_cast<const float4*>(&Vs[j][k0]);
            float pa[4] = {p4.x, p4.y, p4.z, p4.w};
            float va[4] = {v4.x, v4.y, v4.z, v4.w};
            #pragma unroll
            for (int a = 0; a < 4; ++a)
                #pragma unroll
                for (int c2 = 0; c2 < 4; ++c2)
                    acc[a][c2] += pa[a] * va[c2];
        }
        #pragma unroll
        for (int a = 0; a < 4; ++a) {
            int i = i0 + a;
            float inv = rowinv[i];
            int hs = (win_h << 3) + (i >> 3);
            int ws = (win_w << 3) + (i & 7);
            int oh = (hs + SS) & 63;            // roll by +ss
            int ow = (ws + SS) & 63;
            int base = ((b * 64 + oh) * 64 + ow) * 512 + head * HD + k0;
            float4 o = make_float4(acc[a][0] * inv, acc[a][1] * inv,
                                   acc[a][2] * inv, acc[a][3] * inv);
            *reinterpret_cast<float4*>(gout + base) = o;
        }
    }
}

}  // namespace

extern "C" void kernel_launch(void* const* d_in, const int* in_sizes, int n_in,
                              void* d_out, int out_size)
{
    (void)in_sizes; (void)n_in; (void)out_size;
    const float* q    = (const float*)d_in[0];
    const float* k    = (const float*)d_in[1];
    const float* v    = (const float*)d_in[2];
    const float* bias = (const float*)d_in[3];
    // 1024 windows * 16 heads = 16384 CTAs, 128 threads each
    swin_attn_kernel<<<16384, 128>>>(q, k, v, bias, (float*)d_out);
}

// round 2
// speedup vs baseline: 1.5940x; 1.5940x over previous
#include <cuda_runtime.h>

namespace {

constexpr int QK_S = 36;   // Q/K row stride (floats): 32 data + 4 pad; 36 mod 32 = 4 -> conflict-free
constexpr int ST_S = 68;   // S row stride: 64 + 4 pad
constexpr int VT_S = 68;   // Vt row stride

__device__ __forceinline__ void fma2(unsigned long long& d,
                                     unsigned long long a,
                                     unsigned long long b) {
    asm("fma.rn.f32x2 %0, %1, %2, %0;" : "+l"(d) : "l"(a), "l"(b));
}

__device__ __forceinline__ float sum2(unsigned long long v) {
    float lo, hi;
    asm("mov.b64 {%0, %1}, %2;" : "=f"(lo), "=f"(hi) : "l"(v));
    return lo + hi;
}

__global__ __launch_bounds__(64)
void swin_attn_kernel(const float* __restrict__ gq,
                      const float* __restrict__ gk,
                      const float* __restrict__ gv,
                      const float* __restrict__ gbias,
                      float* __restrict__ gout)
{
    __shared__ __align__(16) float Qrm[64 * QK_S];  // Q[i][k] * scale, row-major
    __shared__ __align__(16) float Krm[64 * QK_S];  // K[j][k], row-major
    __shared__ __align__(16) float Vt[32 * VT_S];   // V transposed: Vt[k][j]
    __shared__ __align__(16) float St[64 * ST_S];   // exp'd logits, row-major [i][j]
    __shared__ float biasS[225];
    __shared__ float rowinv[64];
    __shared__ int   regS[64];

    const int tid   = threadIdx.x;
    const int head  = blockIdx.x & 15;
    const int wy    = blockIdx.x >> 4;
    const int b     = wy >> 6;
    const int win   = wy & 63;
    const int win_h = win >> 3;
    const int win_w = win & 7;
    const float scale = 0.17677669529663687f;  // 1/sqrt(32)

    // ---- load Q,K,V (gather applies cyclic shift by -4); V stored transposed ----
    #pragma unroll
    for (int it = 0; it < 8; ++it) {
        int f = tid + (it << 6);                // 512 float4 units per tensor
        int n = f >> 3;                         // token in window
        int c = (f & 7) << 2;                   // channel (mult of 4)
        int sh = ((win_h << 3) + (n >> 3) + 4) & 63;
        int sw = ((win_w << 3) + (n & 7) + 4) & 63;
        int base = ((b * 64 + sh) * 64 + sw) * 512 + head * 32 + c;
        float4 qv = *reinterpret_cast<const float4*>(gq + base);
        float4 kv = *reinterpret_cast<const float4*>(gk + base);
        float4 vv = *reinterpret_cast<const float4*>(gv + base);
        qv.x *= scale; qv.y *= scale; qv.z *= scale; qv.w *= scale;
        *reinterpret_cast<float4*>(&Qrm[n * QK_S + c]) = qv;
        *reinterpret_cast<float4*>(&Krm[n * QK_S + c]) = kv;
        Vt[(c + 0) * VT_S + n] = vv.x;
        Vt[(c + 1) * VT_S + n] = vv.y;
        Vt[(c + 2) * VT_S + n] = vv.z;
        Vt[(c + 3) * VT_S + n] = vv.w;
    }
    for (int t = tid; t < 225; t += 64) biasS[t] = gbias[t * 16 + head];
    {
        int hs = (win_h << 3) + (tid >> 3);
        int ws2 = (win_w << 3) + (tid & 7);
        int rh = (hs >= 56) + (hs >= 60);       // H-ws=56, H-ss=60
        int rw = (ws2 >= 56) + (ws2 >= 60);
        regS[tid] = rh * 4 + rw;
    }
    __syncthreads();

    const int ti = tid >> 3;   // 0..7
    const int tj = tid & 7;    // 0..7

    // ---- GEMM1: 8x8 tile per thread, rows i = ti+8t, cols j = tj+8u ----
    // k-pair packed FFMA2: acc2[t][u] accumulates {even k, odd k} partial sums.
    unsigned long long acc[8][8] = {};
    #pragma unroll
    for (int kb = 0; kb < 8; ++kb) {            // 8 blocks of 4 k
        ulonglong2 kv[8];
        #pragma unroll
        for (int u = 0; u < 8; ++u)
            kv[u] = *reinterpret_cast<const ulonglong2*>(&Krm[(tj + 8 * u) * QK_S + (kb << 2)]);
        #pragma unroll
        for (int t = 0; t < 8; ++t) {
            ulonglong2 qv = *reinterpret_cast<const ulonglong2*>(&Qrm[(ti + 8 * t) * QK_S + (kb << 2)]);
            #pragma unroll
            for (int u = 0; u < 8; ++u) {
                fma2(acc[t][u], qv.x, kv[u].x);
                fma2(acc[t][u], qv.y, kv[u].y);
            }
        }
    }

    // ---- fused epilogue: bias + mask + softmax (row lives in 8 adjacent lanes) ----
    int regi[8], regj[8];
    #pragma unroll
    for (int t = 0; t < 8; ++t) regi[t] = regS[ti + 8 * t];
    #pragma unroll
    for (int u = 0; u < 8; ++u) regj[u] = regS[tj + 8 * u];

    #pragma unroll
    for (int t = 0; t < 8; ++t) {
        int i = ti + 8 * t;
        int ih = i >> 3, iw = i & 7;
        float s[8];
        #pragma unroll
        for (int u = 0; u < 8; ++u) {
            int j = tj + 8 * u;
            int idx = (ih - (j >> 3) + 7) * 15 + (iw - (j & 7) + 7);
            float v = sum2(acc[t][u]) + biasS[idx];
            if (regi[t] != regj[u]) v -= 100.0f;
            s[u] = v;
        }
        float mx = s[0];
        #pragma unroll
        for (int u = 1; u < 8; ++u) mx = fmaxf(mx, s[u]);
        mx = fmaxf(mx, __shfl_xor_sync(0xffffffffu, mx, 1));
        mx = fmaxf(mx, __shfl_xor_sync(0xffffffffu, mx, 2));
        mx = fmaxf(mx, __shfl_xor_sync(0xffffffffu, mx, 4));
        float sum = 0.0f;
        #pragma unroll
        for (int u = 0; u < 8; ++u) {
            float p = __expf(s[u] - mx);
            s[u] = p;
            sum += p;
        }
        sum += __shfl_xor_sync(0xffffffffu, sum, 1);
        sum += __shfl_xor_sync(0xffffffffu, sum, 2);
        sum += __shfl_xor_sync(0xffffffffu, sum, 4);
        #pragma unroll
        for (int u = 0; u < 8; ++u) St[i * ST_S + tj + 8 * u] = s[u];
        if (tj == 0) rowinv[i] = 1.0f / sum;
    }
    __syncthreads();

    // ---- GEMM2: O = P @ V. 8x4 tile: rows i = ti+8t, cols k = tj+8v. j-pair FFMA2. ----
    unsigned long long acc2[8][4] = {};
    #pragma unroll
    for (int jb = 0; jb < 16; ++jb) {           // 16 blocks of 4 j
        ulonglong2 vv[4];
        #pragma unroll
        for (int v = 0; v < 4; ++v)
            vv[v] = *reinterpret_cast<const ulonglong2*>(&Vt[(tj + 8 * v) * VT_S + (jb << 2)]);
        #pragma unroll
        for (int t = 0; t < 8; ++t) {
            ulonglong2 pv = *reinterpret_cast<const ulonglong2*>(&St[(ti + 8 * t) * ST_S + (jb << 2)]);
            #pragma unroll
            for (int v = 0; v < 4; ++v) {
                fma2(acc2[t][v], pv.x, vv[v].x);
                fma2(acc2[t][v], pv.y, vv[v].y);
            }
        }
    }

    // ---- normalize + scatter (reverse cyclic shift by +4) ----
    #pragma unroll
    for (int t = 0; t < 8; ++t) {
        int i = ti + 8 * t;
        float inv = rowinv[i];
        int hs = (win_h << 3) + (i >> 3);
        int ws2 = (win_w << 3) + (i & 7);
        int oh = (hs + 4) & 63;
        int ow = (ws2 + 4) & 63;
        int base = ((b * 64 + oh) * 64 + ow) * 512 + head * 32;
        #pragma unroll
        for (int v = 0; v < 4; ++v)
            gout[base + tj + 8 * v] = sum2(acc2[t][v]) * inv;
    }
}

}  // namespace

extern "C" void kernel_launch(void* const* d_in, const int* in_sizes, int n_in,
                              void* d_out, int out_size)
{
    (void)in_sizes; (void)n_in; (void)out_size;
    const float* q    = (const float*)d_in[0];
    const float* k    = (const float*)d_in[1];
    const float* v    = (const float*)d_in[2];
    const float* bias = (const float*)d_in[3];
    swin_attn_kernel<<<16384, 64>>>(q, k, v, bias, (float*)d_out);
}

// round 4
// speedup vs baseline: 2.6642x; 1.6714x over previous
#include <cuda_runtime.h>
#include <cstdint>

namespace {

// smem word offsets
constexpr int QH = 0;       // Q hi tf32, stride 36, 64 rows
constexpr int QL = 2304;    // Q lo
constexpr int KH = 4608;    // K hi
constexpr int KL = 6912;    // K lo
constexpr int VO = 9216;    // V tf32, stride 40, 64 rows
constexpr int BI = 11776;   // bias, 225 floats
constexpr int RG = 12004;   // region ids, 64 ints
constexpr int SMW = 12068;  // 48272 bytes (static, fits 48KB)
constexpr int PO = 0;       // P overlays QH/QL, stride 68, 64 rows (4352 words < 4608)

__device__ __forceinline__ uint32_t cvt_tf32(float x) {
    uint32_t u;
    asm("cvt.rna.tf32.f32 %0, %1;" : "=r"(u) : "f"(x));
    return u;
}

__device__ __forceinline__ void mma8(float* c, const uint32_t* a, uint32_t b0, uint32_t b1) {
    asm volatile("mma.sync.aligned.m16n8k8.row.col.f32.tf32.tf32.f32 "
        "{%0,%1,%2,%3}, {%4,%5,%6,%7}, {%8,%9}, {%0,%1,%2,%3};"
        : "+f"(c[0]), "+f"(c[1]), "+f"(c[2]), "+f"(c[3])
        : "r"(a[0]), "r"(a[1]), "r"(a[2]), "r"(a[3]), "r"(b0), "r"(b1));
}

__global__ __launch_bounds__(128, 4)
void swin_mma_kernel(const float* __restrict__ gq, const float* __restrict__ gk,
                     const float* __restrict__ gv, const float* __restrict__ gbias,
                     float* __restrict__ gout)
{
    __shared__ uint32_t SM[SMW];

    const int tid   = threadIdx.x;
    const int head  = blockIdx.x & 15;
    const int wy    = blockIdx.x >> 4;
    const int b     = wy >> 6;
    const int win   = wy & 63;
    const int win_h = win >> 3, win_w = win & 7;
    const float scale = 0.17677669529663687f;   // 1/sqrt(32)

    // ---- load Q,K,V (gather applies cyclic shift -4), split to tf32 hi/lo ----
    #pragma unroll
    for (int r = 0; r < 4; ++r) {
        int u = tid + (r << 7);               // 0..511
        int t = u >> 3;                       // token
        int cq = u & 7;                       // channel quad
        int sh  = ((win_h << 3) + (t >> 3) + 4) & 63;
        int sw2 = ((win_w << 3) + (t & 7) + 4) & 63;
        int gbase = ((((b << 6) + sh) << 6) + sw2) * 512 + head * 32 + (cq << 2);
        float4 q = *reinterpret_cast<const float4*>(gq + gbase);
        float4 k = *reinterpret_cast<const float4*>(gk + gbase);
        float4 v = *reinterpret_cast<const float4*>(gv + gbase);
        q.x *= scale; q.y *= scale; q.z *= scale; q.w *= scale;
        uint4 qh, ql, kh, kl, vt;
        qh.x = cvt_tf32(q.x); ql.x = cvt_tf32(q.x - __uint_as_float(qh.x));
        qh.y = cvt_tf32(q.y); ql.y = cvt_tf32(q.y - __uint_as_float(qh.y));
        qh.z = cvt_tf32(q.z); ql.z = cvt_tf32(q.z - __uint_as_float(qh.z));
        qh.w = cvt_tf32(q.w); ql.w = cvt_tf32(q.w - __uint_as_float(qh.w));
        kh.x = cvt_tf32(k.x); kl.x = cvt_tf32(k.x - __uint_as_float(kh.x));
        kh.y = cvt_tf32(k.y); kl.y = cvt_tf32(k.y - __uint_as_float(kh.y));
        kh.z = cvt_tf32(k.z); kl.z = cvt_tf32(k.z - __uint_as_float(kh.z));
        kh.w = cvt_tf32(k.w); kl.w = cvt_tf32(k.w - __uint_as_float(kh.w));
        vt.x = cvt_tf32(v.x); vt.y = cvt_tf32(v.y);
        vt.z = cvt_tf32(v.z); vt.w = cvt_tf32(v.w);
        int o36 = t * 36 + (cq << 2);
        *reinterpret_cast<uint4*>(&SM[QH + o36]) = qh;
        *reinterpret_cast<uint4*>(&SM[QL + o36]) = ql;
        *reinterpret_cast<uint4*>(&SM[KH + o36]) = kh;
        *reinterpret_cast<uint4*>(&SM[KL + o36]) = kl;
        *reinterpret_cast<uint4*>(&SM[VO + t * 40 + (cq << 2)]) = vt;
    }
    for (int t = tid; t < 225; t += 128)
        reinterpret_cast<float*>(SM)[BI + t] = gbias[t * 16 + head];
    if (tid < 64) {
        int hs  = (win_h << 3) + (tid >> 3);
        int wsx = (win_w << 3) + (tid & 7);
        int rh = (hs >= 56) + (hs >= 60);
        int rw = (wsx >= 56) + (wsx >= 60);
        reinterpret_cast<int*>(SM)[RG + tid] = rh * 4 + rw;
    }
    __syncthreads();

    const int w    = tid >> 5;
    const int lane = tid & 31;
    const int g    = lane >> 2;    // group (row within fragment)
    const int t4   = lane & 3;
    const int m0   = w << 4;
    const int iA   = m0 + g;       // first row (token)
    const int iB   = m0 + g + 8;   // second row

    // ---- QK: 3xTF32 (qh*kh + ql*kh + qh*kl), 8 n-tiles, 4 k-steps ----
    float c[8][4] = {};
    #pragma unroll
    for (int ks = 0; ks < 4; ++ks) {
        int k0 = ks << 3;
        uint32_t ah[4], al[4];
        int oa0 = iA * 36 + k0 + t4, ob0 = iB * 36 + k0 + t4;
        ah[0] = SM[QH + oa0];     ah[1] = SM[QH + ob0];
        ah[2] = SM[QH + oa0 + 4]; ah[3] = SM[QH + ob0 + 4];
        al[0] = SM[QL + oa0];     al[1] = SM[QL + ob0];
        al[2] = SM[QL + oa0 + 4]; al[3] = SM[QL + ob0 + 4];
        #pragma unroll
        for (int nt = 0; nt < 8; ++nt) {
            int kb = ((nt << 3) + g) * 36 + k0 + t4;
            uint32_t bh0 = SM[KH + kb], bh1 = SM[KH + kb + 4];
            uint32_t bl0 = SM[KL + kb], bl1 = SM[KL + kb + 4];
            mma8(c[nt], ah, bh0, bh1);
            mma8(c[nt], al, bh0, bh1);
            mma8(c[nt], ah, bl0, bl1);
        }
    }
    __syncthreads();   // all Q/K fragment reads done; QH/QL region free for P overlay

    // ---- epilogue: bias + mask + softmax (rows iA, iB per thread) ----
    const int*   regp = reinterpret_cast<const int*>(SM) + RG;
    const float* bias = reinterpret_cast<const float*>(SM) + BI;
    const int regA = regp[iA], regB = regp[iB];
    const int bA = 15 * (iA >> 3) + (iA & 7) + 112;
    const int bB = 15 * (iB >> 3) + (iB & 7) + 112;

    float mA = -1e30f, mB = -1e30f;
    #pragma unroll
    for (int nt = 0; nt < 8; ++nt) {
        #pragma unroll
        for (int q = 0; q < 2; ++q) {
            int j  = (nt << 3) + (t4 << 1) + q;
            int bj = 15 * (j >> 3) + (j & 7);
            int rj = regp[j];
            float xA = c[nt][q]     + bias[bA - bj];
            float xB = c[nt][2 + q] + bias[bB - bj];
            if (rj != regA) xA -= 100.0f;
            if (rj != regB) xB -= 100.0f;
            c[nt][q] = xA; c[nt][2 + q] = xB;
            mA = fmaxf(mA, xA); mB = fmaxf(mB, xB);
        }
    }
    mA = fmaxf(mA, __shfl_xor_sync(0xffffffffu, mA, 1));
    mA = fmaxf(mA, __shfl_xor_sync(0xffffffffu, mA, 2));
    mB = fmaxf(mB, __shfl_xor_sync(0xffffffffu, mB, 1));
    mB = fmaxf(mB, __shfl_xor_sync(0xffffffffu, mB, 2));
    float sA = 0.0f, sB = 0.0f;
    #pragma unroll
    for (int nt = 0; nt < 8; ++nt) {
        #pragma unroll
        for (int q = 0; q < 2; ++q) {
            float pA = __expf(c[nt][q] - mA);
            float pB = __expf(c[nt][2 + q] - mB);
            c[nt][q] = pA; c[nt][2 + q] = pB;
            sA += pA; sB += pB;
        }
    }
    sA += __shfl_xor_sync(0xffffffffu, sA, 1);
    sA += __shfl_xor_sync(0xffffffffu, sA, 2);
    sB += __shfl_xor_sync(0xffffffffu, sB, 1);
    sB += __shfl_xor_sync(0xffffffffu, sB, 2);
    const float invA = 1.0f / sA, invB = 1.0f / sB;

    // write normalized P (tf32) to smem, stride 68
    #pragma unroll
    for (int nt = 0; nt < 8; ++nt) {
        int jc = (nt << 3) + (t4 << 1);
        uint2 pa, pb;
        pa.x = cvt_tf32(c[nt][0] * invA); pa.y = cvt_tf32(c[nt][1] * invA);
        pb.x = cvt_tf32(c[nt][2] * invB); pb.y = cvt_tf32(c[nt][3] * invB);
        *reinterpret_cast<uint2*>(&SM[PO + iA * 68 + jc]) = pa;
        *reinterpret_cast<uint2*>(&SM[PO + iB * 68 + jc]) = pb;
    }
    __syncwarp();

    // ---- PV: O(16x32 strip) = P @ V, K=64 (8 k-steps), 4 n-tiles ----
    float o[4][4] = {};
    #pragma unroll
    for (int ks = 0; ks < 8; ++ks) {
        int k0 = ks << 3;
        uint32_t a[4];
        a[0] = SM[PO + iA * 68 + k0 + t4];
        a[1] = SM[PO + iB * 68 + k0 + t4];
        a[2] = SM[PO + iA * 68 + k0 + t4 + 4];
        a[3] = SM[PO + iB * 68 + k0 + t4 + 4];
        #pragma unroll
        for (int nt = 0; nt < 4; ++nt) {
            int n0 = nt << 3;
            uint32_t b0 = SM[VO + (k0 + t4) * 40 + n0 + g];
            uint32_t b1 = SM[VO + (k0 + t4 + 4) * 40 + n0 + g];
            mma8(o[nt], a, b0, b1);
        }
    }

    // ---- store (reverse cyclic shift +4) ----
    {
        int ohA = ((win_h << 3) + (iA >> 3) + 4) & 63;
        int owA = ((win_w << 3) + (iA & 7) + 4) & 63;
        int ohB = ((win_h << 3) + (iB >> 3) + 4) & 63;
        int owB = ((win_w << 3) + (iB & 7) + 4) & 63;
        float* dA = gout + ((((b << 6) + ohA) << 6) + owA) * 512 + head * 32 + (t4 << 1);
        float* dB = gout + ((((b << 6) + ohB) << 6) + owB) * 512 + head * 32 + (t4 << 1);
        #pragma unroll
        for (int nt = 0; nt < 4; ++nt) {
            *reinterpret_cast<float2*>(dA + (nt << 3)) = make_float2(o[nt][0], o[nt][1]);
            *reinterpret_cast<float2*>(dB + (nt << 3)) = make_float2(o[nt][2], o[nt][3]);
        }
    }
}

}  // namespace

extern "C" void kernel_launch(void* const* d_in, const int* in_sizes, int n_in,
                              void* d_out, int out_size)
{
    (void)in_sizes; (void)n_in; (void)out_size;
    const float* q    = (const float*)d_in[0];
    const float* k    = (const float*)d_in[1];
    const float* v    = (const float*)d_in[2];
    const float* bias = (const float*)d_in[3];
    swin_mma_kernel<<<16384, 128>>>(q, k, v, bias, (float*)d_out);
}